// round 11
// baseline (speedup 1.0000x reference)
#include <cuda_runtime.h>
#include <math.h>
#include <stdint.h>

#if defined(__CUDA_ARCH_FEAT_SM103_ALL) || defined(__CUDA_ARCH_FEAT_SM100_ALL) || defined(__CUDA_ARCH_FEAT_SM101_ALL) || defined(__CUDA_ARCH_FEAT_SM110_ALL)
#define HAS_TC 1
#else
#define HAS_TC 0
#endif

// Problem dims
constexpr int Bd = 8;
constexpr int Sd = 1024;
constexpr int Ed = 1024;
constexpr int Fd = 4096;
constexpr int MTOT = Bd * Sd;   // 8192

// tcgen05 GEMM tile config (proven R9/R10): 256x256 tile = 2 x (128x256) MMA
constexpr int TMM = 256;
constexpr int TN = 256;
constexpr int TK = 32;          // K elems per stage
constexpr int NS = 3;           // pipeline stages
constexpr int STAGE_BYTES = (TMM + TN) * 128;           // 65536
constexpr int SMEM_TOTAL = 1024 + NS * STAGE_BYTES;     // 197632
constexpr int NTHREADS = 288;   // 4 producer + 4 epilogue + 1 MMA warp
constexpr int GRID = 128;       // all co-resident (1 CTA/SM, 128 <= 148 SMs)

constexpr uint32_t IDESC =
    (1u << 4) | (2u << 7) | (2u << 10) | ((TN / 8) << 17) | ((128 / 16) << 24);

#define OFF_TMEM   0
#define OFF_FULL(s)  (8 + 8*(s))
#define OFF_EMPTY(s) (8 + 8*NS + 8*(s))
#define OFF_FIN      (8 + 16*NS)
#define OFF_TFREE    (8 + 16*NS + 8)

// ---------------- scratch (device globals) ---------------------------------
__device__ float g_xr  [(long long)MTOT * Ed];
__device__ float g_qk  [(long long)2 * MTOT * Ed];
__device__ float g_vt  [(long long)MTOT * Ed];
__device__ float g_at  [(long long)Bd * Sd * Sd];
__device__ float g_ao  [(long long)MTOT * Ed];
__device__ float g_tmp [(long long)MTOT * Ed];
__device__ float g_h1  [(long long)MTOT * Ed];
__device__ float g_ff  [(long long)MTOT * Fd];
__device__ float g_wt  [(long long)3 * Ed * Ed];
__device__ float g_b2  [2 * Ed];
__device__ float g_wdt [(long long)Ed * Ed];
__device__ float g_wit [(long long)Fd * Ed];
__device__ float g_wot [(long long)Ed * Fd];

// grid-barrier state (zero-initialized; flags are monotonic across replays,
// counters are reset by the completer each use)
__device__ unsigned g_cnt [16];
__device__ unsigned g_flag[16];

// ---------------- PTX helpers -------------------------------------------------
__device__ __forceinline__ uint32_t smem_u32(const void* p) {
    uint32_t a;
    asm("{ .reg .u64 t; cvta.to.shared.u64 t, %1; cvt.u32.u64 %0, t; }" : "=r"(a) : "l"(p));
    return a;
}
__device__ __forceinline__ uint32_t elect_one() {
    uint32_t p;
    asm volatile("{ .reg .pred p; elect.sync _|p, 0xFFFFFFFF; selp.b32 %0,1,0,p; }" : "=r"(p));
    return p;
}
__device__ __forceinline__ void mbar_init(uint32_t a, uint32_t c) {
    asm volatile("mbarrier.init.shared.b64 [%0], %1;" :: "r"(a), "r"(c) : "memory");
}
__device__ __forceinline__ void mbar_arrive(uint32_t a) {
    asm volatile("mbarrier.arrive.shared.b64 _, [%0];" :: "r"(a) : "memory");
}
__device__ __forceinline__ void mbar_wait(uint32_t a, uint32_t ph) {
    uint32_t done;
    asm volatile(
        "{\n\t.reg .pred p;\n\t"
        "mbarrier.try_wait.parity.acquire.cta.shared::cta.b64 p, [%1], %2;\n\t"
        "selp.b32 %0, 1, 0, p;\n\t}"
        : "=r"(done) : "r"(a), "r"(ph) : "memory");
    if (!done) {
        asm volatile(
            "{\n\t.reg .pred P1;\n\t"
            "WL%=:\n\t"
            "mbarrier.try_wait.parity.acquire.cta.shared::cta.b64 P1, [%0], %1, 0x989680;\n\t"
            "@P1 bra.uni WD%=;\n\t"
            "bra.uni WL%=;\n\t"
            "WD%=:\n\t}"
            :: "r"(a), "r"(ph) : "memory");
    }
}
__device__ __forceinline__ void cp16(uint32_t dst, const void* src) {
    asm volatile("cp.async.cg.shared.global [%0], [%1], 16;" :: "r"(dst), "l"(src) : "memory");
}
__device__ __forceinline__ void cpasync_arrive(uint32_t a) {
    asm volatile("cp.async.mbarrier.arrive.noinc.shared::cta.b64 [%0];" :: "r"(a) : "memory");
}
__device__ __forceinline__ uint64_t make_desc(uint32_t addr) {
    return 0x4000404000010000ULL | ((uint64_t)(addr >> 4) & 0x3FFF);
}
__device__ __forceinline__ float rna_tf32(float x) {
    uint32_t u;
    asm("cvt.rna.tf32.f32 %0, %1;" : "=r"(u) : "f"(x));
    return __uint_as_float(u);
}
__device__ __forceinline__ void bar256() {
    asm volatile("bar.sync 1, 256;" ::: "memory");
}

// Device-wide barrier: all GRID CTAs co-resident (guaranteed by smem occupancy).
// Flag is monotonic across kernel runs; counter reset by the completer.
__device__ __forceinline__ void grid_bar(int i) {
    __syncthreads();
    if (threadIdx.x == 0) {
        __threadfence();
        unsigned f0 = atomicAdd(&g_flag[i], 0u);
        unsigned old = atomicAdd(&g_cnt[i], 1u);
        if (old == GRID - 1) {
            g_cnt[i] = 0;
            __threadfence();
            atomicAdd(&g_flag[i], 1u);
        } else {
            while (atomicAdd(&g_flag[i], 0u) == f0) __nanosleep(64);
        }
        __threadfence();   // gpu-scope fence -> CCTL.IVALL: invalidate this SM's L1
    }
    __syncthreads();
}

#if HAS_TC
__device__ __forceinline__ void mma_tf32(uint32_t d, uint64_t ad, uint64_t bd,
                                         uint32_t idesc, uint32_t en) {
    asm volatile(
        "{\n\t.reg .pred p;\n\t"
        "setp.ne.u32 p, %4, 0;\n\t"
        "tcgen05.mma.cta_group::1.kind::tf32 [%0], %1, %2, %3, {%5, %5, %5, %5}, p;\n\t}"
        :: "r"(d), "l"(ad), "l"(bd), "r"(idesc), "r"(en), "r"(0u)
        : "memory");
}
#define TC_ALLOC(sa, n)   asm volatile("tcgen05.alloc.cta_group::1.sync.aligned.shared::cta.b32 [%0], %1;" :: "r"(sa), "r"(n) : "memory")
#define TC_DEALLOC(t, n)  asm volatile("tcgen05.dealloc.cta_group::1.sync.aligned.b32 %0, %1;" :: "r"(t), "r"(n))
#define TC_RELINQ()       asm volatile("tcgen05.relinquish_alloc_permit.cta_group::1.sync.aligned;")
#define TC_COMMIT(mb)     asm volatile("tcgen05.commit.cta_group::1.mbarrier::arrive::one.shared::cluster.b64 [%0];" :: "r"(mb) : "memory")
#define TC_FENCE_AFTER()  asm volatile("tcgen05.fence::after_thread_sync;" ::: "memory")
#define TC_FENCE_BEFORE() asm volatile("tcgen05.fence::before_thread_sync;" ::: "memory")
#define TC_WAIT_LD()      asm volatile("tcgen05.wait::ld.sync.aligned;" ::: "memory")

#define LDTM_X32(r, ta) \
    asm volatile( \
        "tcgen05.ld.sync.aligned.32x32b.x32.b32 " \
        "{%0, %1, %2, %3, %4, %5, %6, %7, " \
        " %8, %9, %10, %11, %12, %13, %14, %15, " \
        " %16, %17, %18, %19, %20, %21, %22, %23, " \
        " %24, %25, %26, %27, %28, %29, %30, %31}, [%32];" \
        : "=r"((r)[0]),  "=r"((r)[1]),  "=r"((r)[2]),  "=r"((r)[3]), \
          "=r"((r)[4]),  "=r"((r)[5]),  "=r"((r)[6]),  "=r"((r)[7]), \
          "=r"((r)[8]),  "=r"((r)[9]),  "=r"((r)[10]), "=r"((r)[11]), \
          "=r"((r)[12]), "=r"((r)[13]), "=r"((r)[14]), "=r"((r)[15]), \
          "=r"((r)[16]), "=r"((r)[17]), "=r"((r)[18]), "=r"((r)[19]), \
          "=r"((r)[20]), "=r"((r)[21]), "=r"((r)[22]), "=r"((r)[23]), \
          "=r"((r)[24]), "=r"((r)[25]), "=r"((r)[26]), "=r"((r)[27]), \
          "=r"((r)[28]), "=r"((r)[29]), "=r"((r)[30]), "=r"((r)[31]) \
        : "r"(ta))

// Persistent pipeline state (carried across GEMM phases within one launch).
struct Pipe { int ps; uint32_t eph; int en; int ms; uint32_t mph; int mn; };

// One GEMM phase on the persistent CTAs. Identical mechanics to R10's proven
// tc_gemm, with pipeline counters continuing across calls.
__device__ void run_gemm(uint32_t sb, uint32_t tmem, Pipe* pp,
                         const float* A, const float* Bt,
                         const float* bias, const float* resid, float* C,
                         int K, int N, float alpha,
                         long long sA, long long sB, long long sC, long long sBias,
                         int T, int gx, int gxy, int act, int rnd, int browMode)
{
    const int tid = threadIdx.x;
    const int nk = K / TK;

    if (tid < 128) {
        // ---- producers ----
        int s = pp->ps; uint32_t eph = pp->eph;
        const int a = tid >> 3, c = tid & 7;
        uint32_t o0 = (uint32_t)(a * 128 + c * 16);
        const uint32_t swz = o0 ^ ((o0 >> 3) & 0x70);
        const long long str16 = 16LL * K;
        for (int t = blockIdx.x; t < T; t += GRID) {
            const int tz = t / gxy, rem = t - tz * gxy;
            const int ty = rem / gx, tx = rem - ty * gx;
            const float* pA = A  + (long long)tz * sA + (long long)(ty * TMM + a) * K + c * 4;
            const float* pB = Bt + (long long)tz * sB + (long long)(tx * TN  + a) * K + c * 4;
            for (int kt = 0; kt < nk; kt++) {
                mbar_wait(sb + OFF_EMPTY(s), eph);
                const uint32_t stg = sb + 1024 + s * STAGE_BYTES;
                #pragma unroll
                for (int m = 0; m < 16; m++)
                    cp16(stg + swz + m * 2048, pA + m * str16);
                #pragma unroll
                for (int m = 0; m < 16; m++)
                    cp16(stg + swz + 32768 + m * 2048, pB + m * str16);
                cpasync_arrive(sb + OFF_FULL(s));
                pA += TK; pB += TK;
                if (++s == NS) { s = 0; eph ^= 1; }
            }
        }
        pp->ps = s; pp->eph = eph;
    } else if (tid < 256) {
        // ---- epilogue warps ----
        int n = pp->en;
        const int lane = tid & 31, sp = (tid >> 5) & 3;
        for (int t = blockIdx.x; t < T; t += GRID, n++) {
            mbar_wait(sb + OFF_FIN, n & 1);
            TC_FENCE_AFTER();
            const int tz = t / gxy, rem = t - tz * gxy;
            const int ty = rem / gx, tx = rem - ty * gx;
            const int bm = ty * TMM, bn = tx * TN;
            const float* biasz = bias ? bias + (long long)tz * sBias : nullptr;

            #pragma unroll 1
            for (int h = 0; h < 2; h++) {
                const long long row = bm + h * 128 + sp * 32 + lane;
                float* crow = C + (long long)tz * sC + row * (long long)N + bn;
                const float* rrow = resid ? resid + (long long)tz * sC + row * (long long)N + bn
                                          : nullptr;
                float brv = 0.0f;
                if (browMode && biasz) brv = biasz[row];
                const uint32_t tmh = tmem + h * 256;

                #pragma unroll 1
                for (int cb = 0; cb < 8; cb++) {
                    uint32_t r[32];
                    LDTM_X32(r, tmh + cb * 32);
                    TC_WAIT_LD();
                    float v[32];
                    #pragma unroll
                    for (int j = 0; j < 32; j++) v[j] = __uint_as_float(r[j]) * alpha;
                    if (biasz) {
                        if (browMode) {
                            #pragma unroll
                            for (int j = 0; j < 32; j++) v[j] += brv;
                        } else {
                            #pragma unroll
                            for (int j0 = 0; j0 < 32; j0 += 4) {
                                float4 bb = *reinterpret_cast<const float4*>(biasz + bn + cb * 32 + j0);
                                v[j0+0] += bb.x; v[j0+1] += bb.y; v[j0+2] += bb.z; v[j0+3] += bb.w;
                            }
                        }
                    }
                    if (rrow) {
                        #pragma unroll
                        for (int j0 = 0; j0 < 32; j0 += 4) {
                            float4 rv = *reinterpret_cast<const float4*>(rrow + cb * 32 + j0);
                            v[j0+0] += rv.x; v[j0+1] += rv.y; v[j0+2] += rv.z; v[j0+3] += rv.w;
                        }
                    }
                    if (act) {
                        #pragma unroll
                        for (int j = 0; j < 32; j++)
                            v[j] = 0.5f * v[j] * (1.0f + erff(v[j] * 0.70710678118654752f));
                    }
                    if (rnd) {
                        #pragma unroll
                        for (int j = 0; j < 32; j++) v[j] = rna_tf32(v[j]);
                    }
                    #pragma unroll
                    for (int j0 = 0; j0 < 32; j0 += 4) {
                        float4 o; o.x = v[j0]; o.y = v[j0+1]; o.z = v[j0+2]; o.w = v[j0+3];
                        *reinterpret_cast<float4*>(crow + cb * 32 + j0) = o;
                    }
                }
            }
            TC_FENCE_BEFORE();
            mbar_arrive(sb + OFF_TFREE);
        }
        pp->en = n;
    } else {
        // ---- MMA issuer warp ----
        uint32_t ep = elect_one();
        int s = pp->ms; uint32_t ph = pp->mph; int n = pp->mn;
        for (int t = blockIdx.x; t < T; t += GRID, n++) {
            mbar_wait(sb + OFF_TFREE, (n + 1) & 1);
            TC_FENCE_AFTER();
            for (int kt = 0; kt < nk; kt++) {
                mbar_wait(sb + OFF_FULL(s), ph);
                if (ep) {
                    const uint32_t stg = sb + 1024 + s * STAGE_BYTES;
                    uint64_t ad0 = make_desc(stg);
                    uint64_t ad1 = make_desc(stg + 16384);
                    uint64_t bd  = make_desc(stg + 32768);
                    const uint32_t en0 = (uint32_t)(kt != 0);
                    #pragma unroll
                    for (int j = 0; j < 4; j++) {
                        const uint32_t en = en0 | (uint32_t)(j != 0);
                        mma_tf32(tmem,       ad0 + 2 * j, bd + 2 * j, IDESC, en);
                        mma_tf32(tmem + 256, ad1 + 2 * j, bd + 2 * j, IDESC, en);
                    }
                    TC_COMMIT(sb + OFF_EMPTY(s));
                    if (kt == nk - 1) TC_COMMIT(sb + OFF_FIN);
                }
                if (++s == NS) { s = 0; ph ^= 1; }
            }
        }
        pp->ms = s; pp->mph = ph; pp->mn = n;
    }
}
#endif // HAS_TC

// ---------------- warp-per-row elementwise (all 9 warps, no __syncthreads) ----
__device__ __forceinline__ float warp_sum(float v) {
    #pragma unroll
    for (int o = 16; o; o >>= 1) v += __shfl_xor_sync(0xffffffffu, v, o);
    return v;
}
__device__ __forceinline__ float warp_max(float v) {
    #pragma unroll
    for (int o = 16; o; o >>= 1) v = fmaxf(v, __shfl_xor_sync(0xffffffffu, v, o));
    return v;
}

// softmax over 64 rows of 1024 owned by this CTA (in-place, RNA-rounded)
__device__ void softmax_rows(float* data) {
    const int lane = threadIdx.x & 31, w = threadIdx.x >> 5;
    for (int r = w; r < 64; r += 9) {
        float4* p = reinterpret_cast<float4*>(data + ((long long)blockIdx.x * 64 + r) * 1024);
        float4 v[8];
        float mx = -INFINITY;
        #pragma unroll
        for (int i = 0; i < 8; i++) {
            v[i] = p[i * 32 + lane];
            mx = fmaxf(mx, fmaxf(fmaxf(v[i].x, v[i].y), fmaxf(v[i].z, v[i].w)));
        }
        mx = warp_max(mx);
        float s = 0.f;
        #pragma unroll
        for (int i = 0; i < 8; i++) {
            v[i].x = expf(v[i].x - mx); v[i].y = expf(v[i].y - mx);
            v[i].z = expf(v[i].z - mx); v[i].w = expf(v[i].w - mx);
            s += v[i].x + v[i].y + v[i].z + v[i].w;
        }
        s = warp_sum(s);
        const float inv = 1.0f / s;
        #pragma unroll
        for (int i = 0; i < 8; i++) {
            float4 o;
            o.x = rna_tf32(v[i].x * inv); o.y = rna_tf32(v[i].y * inv);
            o.z = rna_tf32(v[i].z * inv); o.w = rna_tf32(v[i].w * inv);
            p[i * 32 + lane] = o;
        }
    }
}

// LayerNorm over 64 rows of 1024 owned by this CTA
__device__ void ln_rows(const float* in, const float* g, const float* b,
                        float* out, int rnd) {
    const int lane = threadIdx.x & 31, w = threadIdx.x >> 5;
    for (int r = w; r < 64; r += 9) {
        const long long row = (long long)blockIdx.x * 64 + r;
        const float4* p = reinterpret_cast<const float4*>(in + row * 1024);
        float4 v[8];
        float s = 0.f;
        #pragma unroll
        for (int i = 0; i < 8; i++) {
            v[i] = p[i * 32 + lane];
            s += v[i].x + v[i].y + v[i].z + v[i].w;
        }
        s = warp_sum(s);
        const float mu = s * (1.0f / 1024.0f);
        float ss = 0.f;
        #pragma unroll
        for (int i = 0; i < 8; i++) {
            v[i].x -= mu; v[i].y -= mu; v[i].z -= mu; v[i].w -= mu;
            ss += v[i].x * v[i].x + v[i].y * v[i].y + v[i].z * v[i].z + v[i].w * v[i].w;
        }
        ss = warp_sum(ss);
        const float rstd = rsqrtf(ss * (1.0f / 1024.0f) + 1e-12f);
        float4* q = reinterpret_cast<float4*>(out + row * 1024);
        #pragma unroll
        for (int i = 0; i < 8; i++) {
            float4 gg = reinterpret_cast<const float4*>(g)[i * 32 + lane];
            float4 bb = reinterpret_cast<const float4*>(b)[i * 32 + lane];
            float4 o;
            o.x = v[i].x * rstd * gg.x + bb.x;
            o.y = v[i].y * rstd * gg.y + bb.y;
            o.z = v[i].z * rstd * gg.z + bb.z;
            o.w = v[i].w * rstd * gg.w + bb.w;
            if (rnd) {
                o.x = rna_tf32(o.x); o.y = rna_tf32(o.y);
                o.z = rna_tf32(o.z); o.w = rna_tf32(o.w);
            }
            q[i * 32 + lane] = o;
        }
    }
}

// 64x64 transpose tile with named barrier (threads 0..255 only)
__device__ void tbody(const float* in, float* out, int R, int C,
                      int r0, int c0, float* t /* [64][65] scratch */) {
    const int fc = (threadIdx.x & 15) * 4;
    const int fr = threadIdx.x >> 4;          // 0..15
    #pragma unroll
    for (int i = 0; i < 4; i++) {
        const int r = fr + i * 16;
        float4 x = *reinterpret_cast<const float4*>(in + (long long)(r0 + r) * C + c0 + fc);
        t[(fc + 0) * 65 + r] = x.x; t[(fc + 1) * 65 + r] = x.y;
        t[(fc + 2) * 65 + r] = x.z; t[(fc + 3) * 65 + r] = x.w;
    }
    bar256();
    #pragma unroll
    for (int i = 0; i < 4; i++) {
        const int oc = fr + i * 16;
        float4 y;
        y.x = rna_tf32(t[oc * 65 + fc + 0]); y.y = rna_tf32(t[oc * 65 + fc + 1]);
        y.z = rna_tf32(t[oc * 65 + fc + 2]); y.w = rna_tf32(t[oc * 65 + fc + 3]);
        *reinterpret_cast<float4*>(out + (long long)(c0 + oc) * R + r0 + fc) = y;
    }
    bar256();   // protect scratch reuse across jobs
}

// ---------------- the mega kernel ----------------------------------------------
__global__ void __launch_bounds__(NTHREADS, 1)
bert_mega(const float* __restrict__ x,
          const float* __restrict__ Wq, const float* __restrict__ bq,
          const float* __restrict__ Wk, const float* __restrict__ bk,
          const float* __restrict__ Wv, const float* __restrict__ bv,
          const float* __restrict__ Wd, const float* __restrict__ bd,
          const float* __restrict__ g1, const float* __restrict__ b1,
          const float* __restrict__ Wi, const float* __restrict__ bi,
          const float* __restrict__ Wo, const float* __restrict__ bo,
          const float* __restrict__ g2, const float* __restrict__ b2,
          float* __restrict__ out,
          float* xr, float* qk, float* vt, float* at, float* ao,
          float* tmp, float* h1, float* ff,
          float* wt, float* b2qk, float* wdt, float* wit, float* wot)
{
#if HAS_TC
    extern __shared__ char smem[];
    const uint32_t sb = smem_u32(smem);
    const int tid = threadIdx.x;
    const int wid = tid >> 5;

    const long long ME = (long long)MTOT * Ed;
    const long long SE = (long long)Sd * Ed;
    const long long SS = (long long)Sd * Sd;
    const long long EE = (long long)Ed * Ed;

    if (tid == 0) {
        for (int s = 0; s < NS; s++) {
            mbar_init(sb + OFF_FULL(s), 128);
            mbar_init(sb + OFF_EMPTY(s), 1);
        }
        mbar_init(sb + OFF_FIN, 1);
        mbar_init(sb + OFF_TFREE, 128);
    }
    if (wid == 8) {
        TC_ALLOC(sb + OFF_TMEM, 512);
        TC_RELINQ();
    }
    __syncthreads();
    uint32_t tmem;
    asm volatile("ld.shared.b32 %0, [%1];" : "=r"(tmem) : "r"(sb + OFF_TMEM));

    // ---- P0: prep (round x, bias concat, 6 weight transposes) ----
    {
        // round x -> xr (grid-stride over 2M float4)
        const long long n4 = ME / 4;
        for (long long i = (long long)blockIdx.x * NTHREADS + tid; i < n4;
             i += (long long)GRID * NTHREADS) {
            float4 v = reinterpret_cast<const float4*>(x)[i];
            v.x = rna_tf32(v.x); v.y = rna_tf32(v.y);
            v.z = rna_tf32(v.z); v.w = rna_tf32(v.w);
            reinterpret_cast<float4*>(xr)[i] = v;
        }
        // bias concat (CTA 0)
        if (blockIdx.x == 0) {
            for (int i = tid; i < 512; i += NTHREADS) {
                reinterpret_cast<float4*>(b2qk)[i] =
                    (i < 256) ? reinterpret_cast<const float4*>(bq)[i]
                              : reinterpret_cast<const float4*>(bk)[i - 256];
            }
        }
        // transposes: 3072 64x64 jobs over 128 CTAs (threads 0..255)
        if (tid < 256) {
            float* tsc = reinterpret_cast<float*>(smem + 1024);
            for (int job = blockIdx.x; job < 3072; job += GRID) {
                if (job < 1024) {
                    const int w = job >> 8, idx = job & 255;
                    const int ry = idx >> 4, cx = idx & 15;
                    const float* in = w == 0 ? Wq : w == 1 ? Wk : w == 2 ? Wv : Wd;
                    float* o = w == 0 ? wt : w == 1 ? wt + EE : w == 2 ? wt + 2 * EE : wdt;
                    tbody(in, o, 1024, 1024, ry * 64, cx * 64, tsc);
                } else if (job < 2048) {
                    const int idx = job - 1024;
                    const int cx = idx & 63, ry = idx >> 6;     // Wi [Ed,Fd]
                    tbody(Wi, wit, Ed, Fd, ry * 64, cx * 64, tsc);
                } else {
                    const int idx = job - 2048;
                    const int cx = idx & 15, ry = idx >> 4;     // Wo [Fd,Ed]
                    tbody(Wo, wot, Fd, Ed, ry * 64, cx * 64, tsc);
                }
            }
        }
    }
    grid_bar(0);

    Pipe pp = {0, 1u, 0, 0, 0u, 0};

    // ---- P1a: Q,K projections (T=256) + P1b: V^T (T=128), no barrier between ----
    run_gemm(sb, tmem, &pp, xr, wt, b2qk, nullptr, qk,
             Ed, Ed, 1.0f, 0, EE, ME, Ed, 256, 4, 128, 0, 1, 0);
    run_gemm(sb, tmem, &pp, wt + 2 * EE, xr, bv, nullptr, vt,
             Ed, Sd, 1.0f, 0, SE, SE, 0, 128, 4, 16, 0, 1, 1);
    grid_bar(1);

    // ---- P2: scores = q @ k^T / 32 ----
    run_gemm(sb, tmem, &pp, qk, qk + ME, nullptr, nullptr, at,
             Ed, Sd, 0.03125f, SE, SE, SS, 0, 128, 4, 16, 0, 0, 0);
    grid_bar(2);

    // ---- P3: softmax ----
    softmax_rows(at);
    grid_bar(3);

    // ---- P4: attn_out = attn_w @ v ----
    run_gemm(sb, tmem, &pp, at, vt, nullptr, nullptr, ao,
             Sd, Ed, 1.0f, SS, SE, SE, 0, 128, 4, 16, 0, 1, 0);
    grid_bar(4);

    // ---- P5: tmp = ao @ Wd + bd + x ----
    run_gemm(sb, tmem, &pp, ao, wdt, bd, x, tmp,
             Ed, Ed, 1.0f, 0, 0, 0, 0, 128, 4, 128, 0, 0, 0);
    grid_bar(5);

    // ---- P6: h1 = LN(tmp) (rounded) ----
    ln_rows(tmp, g1, b1, h1, 1);
    grid_bar(6);

    // ---- P7: ff = gelu(h1 @ Wi + bi) (rounded) ----
    run_gemm(sb, tmem, &pp, h1, wit, bi, nullptr, ff,
             Ed, Fd, 1.0f, 0, 0, 0, 0, 512, 16, 512, 1, 1, 0);
    grid_bar(7);

    // ---- P8: tmp = ff @ Wo + bo + h1 ----
    run_gemm(sb, tmem, &pp, ff, wot, bo, h1, tmp,
             Fd, Ed, 1.0f, 0, 0, 0, 0, 128, 4, 128, 0, 0, 0);
    grid_bar(8);

    // ---- P9: out = LN(tmp) ----
    ln_rows(tmp, g2, b2, out, 0);

    __syncthreads();
    if (wid == 8) TC_DEALLOC(tmem, 512);
#endif // HAS_TC
}

// ---------------- host launcher -----------------------------------------------
extern "C" void kernel_launch(void* const* d_in, const int* in_sizes, int n_in,
                              void* d_out, int out_size)
{
    const float* x  = (const float*)d_in[0];
    const float* Wq = (const float*)d_in[1];
    const float* bq = (const float*)d_in[2];
    const float* Wk = (const float*)d_in[3];
    const float* bk = (const float*)d_in[4];
    const float* Wv = (const float*)d_in[5];
    const float* bv = (const float*)d_in[6];
    const float* Wd = (const float*)d_in[7];
    const float* bd = (const float*)d_in[8];
    const float* g1 = (const float*)d_in[9];
    const float* b1 = (const float*)d_in[10];
    const float* Wi = (const float*)d_in[11];
    const float* bi = (const float*)d_in[12];
    const float* Wo = (const float*)d_in[13];
    const float* bo = (const float*)d_in[14];
    const float* g2 = (const float*)d_in[15];
    const float* b2 = (const float*)d_in[16];
    float* out = (float*)d_out;

    float *xr, *qk, *vt, *at, *ao, *tmp, *h1, *ff;
    float *wt, *b2qk, *wdt, *wit, *wot;
    cudaGetSymbolAddress((void**)&xr,   g_xr);
    cudaGetSymbolAddress((void**)&qk,   g_qk);
    cudaGetSymbolAddress((void**)&vt,   g_vt);
    cudaGetSymbolAddress((void**)&at,   g_at);
    cudaGetSymbolAddress((void**)&ao,   g_ao);
    cudaGetSymbolAddress((void**)&tmp,  g_tmp);
    cudaGetSymbolAddress((void**)&h1,   g_h1);
    cudaGetSymbolAddress((void**)&ff,   g_ff);
    cudaGetSymbolAddress((void**)&wt,   g_wt);
    cudaGetSymbolAddress((void**)&b2qk, g_b2);
    cudaGetSymbolAddress((void**)&wdt,  g_wdt);
    cudaGetSymbolAddress((void**)&wit,  g_wit);
    cudaGetSymbolAddress((void**)&wot,  g_wot);

    cudaFuncSetAttribute(bert_mega, cudaFuncAttributeMaxDynamicSharedMemorySize, SMEM_TOTAL);

    bert_mega<<<GRID, NTHREADS, SMEM_TOTAL>>>(
        x, Wq, bq, Wk, bk, Wv, bv, Wd, bd, g1, b1, Wi, bi, Wo, bo, g2, b2, out,
        xr, qk, vt, at, ao, tmp, h1, ff, wt, b2qk, wdt, wit, wot);
}

// round 12
// speedup vs baseline: 1.0437x; 1.0437x over previous
#include <cuda_runtime.h>
#include <math.h>
#include <stdint.h>

#if defined(__CUDA_ARCH_FEAT_SM103_ALL) || defined(__CUDA_ARCH_FEAT_SM100_ALL) || defined(__CUDA_ARCH_FEAT_SM101_ALL) || defined(__CUDA_ARCH_FEAT_SM110_ALL)
#define HAS_TC 1
#else
#define HAS_TC 0
#endif

// Problem dims
constexpr int Bd = 8;
constexpr int Sd = 1024;
constexpr int Ed = 1024;
constexpr int Fd = 4096;
constexpr int MTOT = Bd * Sd;   // 8192

// tcgen05 GEMM tile config: 256x256 tile = 2 x (128x256) MMA into TMEM halves
constexpr int TMM = 256;
constexpr int TN = 256;
constexpr int TK = 32;          // K elems per stage (128B per row)
constexpr int NS = 3;           // pipeline stages
constexpr int STAGE_BYTES = (TMM + TN) * 128;           // 65536
constexpr int SMEM_TOTAL = 1024 + NS * STAGE_BYTES;     // 197632
constexpr int NTHREADS = 288;   // 4 producer warps + 4 epilogue warps + 1 MMA warp
constexpr int GRID = 128;       // persistent CTAs

// idesc: c=F32(1), a=TF32(2), b=TF32(2), K-major both, N=256, M=128 (per dispatch)
constexpr uint32_t IDESC =
    (1u << 4) | (2u << 7) | (2u << 10) | ((TN / 8) << 17) | ((128 / 16) << 24);

#define OFF_TMEM   0
#define OFF_FULL(s)  (8 + 8*(s))
#define OFF_EMPTY(s) (8 + 8*NS + 8*(s))
#define OFF_FIN      (8 + 16*NS)
#define OFF_TFREE    (8 + 16*NS + 8)

// ---------------- scratch (device globals) ---------------------------------
__device__ float g_xr  [(long long)MTOT * Ed];
__device__ float g_qk  [(long long)2 * MTOT * Ed];   // q | k contiguous
__device__ float g_vt  [(long long)MTOT * Ed];       // V transposed [E,S] per batch
__device__ float g_at  [(long long)Bd * Sd * Sd];
__device__ float g_ao  [(long long)MTOT * Ed];
__device__ float g_tmp [(long long)MTOT * Ed];
__device__ float g_h1  [(long long)MTOT * Ed];
__device__ float g_ff  [(long long)MTOT * Fd];
__device__ float g_wt  [(long long)3 * Ed * Ed];     // Wq^T | Wk^T | Wv^T
__device__ float g_b2  [2 * Ed];
__device__ float g_wdt [(long long)Ed * Ed];
__device__ float g_wit [(long long)Fd * Ed];
__device__ float g_wot [(long long)Ed * Fd];

// ---------------- PDL helpers ---------------------------------------------------
__device__ __forceinline__ void pdl_trigger() {
#if (defined(__CUDA_ARCH__) && __CUDA_ARCH__ >= 900)
    cudaTriggerProgrammaticLaunchCompletion();
#endif
}
__device__ __forceinline__ void pdl_wait() {
#if (defined(__CUDA_ARCH__) && __CUDA_ARCH__ >= 900)
    cudaGridDependencySynchronize();
#endif
}

// ---------------- PTX helpers -------------------------------------------------
__device__ __forceinline__ uint32_t smem_u32(const void* p) {
    uint32_t a;
    asm("{ .reg .u64 t; cvta.to.shared.u64 t, %1; cvt.u32.u64 %0, t; }" : "=r"(a) : "l"(p));
    return a;
}
__device__ __forceinline__ uint32_t elect_one() {
    uint32_t p;
    asm volatile("{ .reg .pred p; elect.sync _|p, 0xFFFFFFFF; selp.b32 %0,1,0,p; }" : "=r"(p));
    return p;
}
__device__ __forceinline__ void mbar_init(uint32_t a, uint32_t c) {
    asm volatile("mbarrier.init.shared.b64 [%0], %1;" :: "r"(a), "r"(c) : "memory");
}
__device__ __forceinline__ void mbar_arrive(uint32_t a) {
    asm volatile("mbarrier.arrive.shared.b64 _, [%0];" :: "r"(a) : "memory");
}
__device__ __forceinline__ void mbar_wait(uint32_t a, uint32_t ph) {
    uint32_t done;
    asm volatile(
        "{\n\t.reg .pred p;\n\t"
        "mbarrier.try_wait.parity.acquire.cta.shared::cta.b64 p, [%1], %2;\n\t"
        "selp.b32 %0, 1, 0, p;\n\t}"
        : "=r"(done) : "r"(a), "r"(ph) : "memory");
    if (!done) {
        asm volatile(
            "{\n\t.reg .pred P1;\n\t"
            "WL%=:\n\t"
            "mbarrier.try_wait.parity.acquire.cta.shared::cta.b64 P1, [%0], %1, 0x989680;\n\t"
            "@P1 bra.uni WD%=;\n\t"
            "bra.uni WL%=;\n\t"
            "WD%=:\n\t}"
            :: "r"(a), "r"(ph) : "memory");
    }
}
__device__ __forceinline__ void cp16(uint32_t dst, const void* src) {
    asm volatile("cp.async.cg.shared.global [%0], [%1], 16;" :: "r"(dst), "l"(src) : "memory");
}
__device__ __forceinline__ void cpasync_arrive(uint32_t a) {
    asm volatile("cp.async.mbarrier.arrive.noinc.shared::cta.b64 [%0];" :: "r"(a) : "memory");
}
__device__ __forceinline__ uint64_t make_desc(uint32_t addr) {
    return 0x4000404000010000ULL | ((uint64_t)(addr >> 4) & 0x3FFF);
}
__device__ __forceinline__ float rna_tf32(float x) {
    uint32_t u;
    asm("cvt.rna.tf32.f32 %0, %1;" : "=r"(u) : "f"(x));
    return __uint_as_float(u);
}

#if HAS_TC
__device__ __forceinline__ void mma_tf32(uint32_t d, uint64_t ad, uint64_t bd,
                                         uint32_t idesc, uint32_t en) {
    asm volatile(
        "{\n\t.reg .pred p;\n\t"
        "setp.ne.u32 p, %4, 0;\n\t"
        "tcgen05.mma.cta_group::1.kind::tf32 [%0], %1, %2, %3, {%5, %5, %5, %5}, p;\n\t}"
        :: "r"(d), "l"(ad), "l"(bd), "r"(idesc), "r"(en), "r"(0u)
        : "memory");
}
#define TC_ALLOC(sa, n)   asm volatile("tcgen05.alloc.cta_group::1.sync.aligned.shared::cta.b32 [%0], %1;" :: "r"(sa), "r"(n) : "memory")
#define TC_DEALLOC(t, n)  asm volatile("tcgen05.dealloc.cta_group::1.sync.aligned.b32 %0, %1;" :: "r"(t), "r"(n))
#define TC_RELINQ()       asm volatile("tcgen05.relinquish_alloc_permit.cta_group::1.sync.aligned;")
#define TC_COMMIT(mb)     asm volatile("tcgen05.commit.cta_group::1.mbarrier::arrive::one.shared::cluster.b64 [%0];" :: "r"(mb) : "memory")
#define TC_FENCE_AFTER()  asm volatile("tcgen05.fence::after_thread_sync;" ::: "memory")
#define TC_FENCE_BEFORE() asm volatile("tcgen05.fence::before_thread_sync;" ::: "memory")
#define TC_WAIT_LD()      asm volatile("tcgen05.wait::ld.sync.aligned;" ::: "memory")

#define LDTM_X32(r, ta) \
    asm volatile( \
        "tcgen05.ld.sync.aligned.32x32b.x32.b32 " \
        "{%0, %1, %2, %3, %4, %5, %6, %7, " \
        " %8, %9, %10, %11, %12, %13, %14, %15, " \
        " %16, %17, %18, %19, %20, %21, %22, %23, " \
        " %24, %25, %26, %27, %28, %29, %30, %31}, [%32];" \
        : "=r"((r)[0]),  "=r"((r)[1]),  "=r"((r)[2]),  "=r"((r)[3]), \
          "=r"((r)[4]),  "=r"((r)[5]),  "=r"((r)[6]),  "=r"((r)[7]), \
          "=r"((r)[8]),  "=r"((r)[9]),  "=r"((r)[10]), "=r"((r)[11]), \
          "=r"((r)[12]), "=r"((r)[13]), "=r"((r)[14]), "=r"((r)[15]), \
          "=r"((r)[16]), "=r"((r)[17]), "=r"((r)[18]), "=r"((r)[19]), \
          "=r"((r)[20]), "=r"((r)[21]), "=r"((r)[22]), "=r"((r)[23]), \
          "=r"((r)[24]), "=r"((r)[25]), "=r"((r)[26]), "=r"((r)[27]), \
          "=r"((r)[28]), "=r"((r)[29]), "=r"((r)[30]), "=r"((r)[31]) \
        : "r"(ta))
#endif // HAS_TC

// ---------------- persistent warp-specialized tcgen05 TF32 GEMM ----------------
// (R10 mechanics, proven) C = act(alpha*A@Bt^T + bias + resid).
template<int ACT, bool ROUND, bool BROW>
__global__ void __launch_bounds__(NTHREADS, 1)
tc_gemm(const float* __restrict__ A, const float* __restrict__ Bt,
        const float* __restrict__ bias, const float* __restrict__ resid,
        float* __restrict__ C, int K, int N, float alpha,
        long long sA, long long sB, long long sC, long long sBias,
        int T, int gx, int gxy)
{
#if HAS_TC
    extern __shared__ char smem[];
    const uint32_t sb = smem_u32(smem);
    const int tid = threadIdx.x;
    const int wid = tid >> 5;
    const int nk = K / TK;

    if (tid == 0) {
        for (int s = 0; s < NS; s++) {
            mbar_init(sb + OFF_FULL(s), 128);
            mbar_init(sb + OFF_EMPTY(s), 1);
        }
        mbar_init(sb + OFF_FIN, 1);
        mbar_init(sb + OFF_TFREE, 128);
    }
    if (wid == 8) {
        TC_ALLOC(sb + OFF_TMEM, 512);
        TC_RELINQ();
    }
    __syncthreads();
    uint32_t tmem;
    asm volatile("ld.shared.b32 %0, [%1];" : "=r"(tmem) : "r"(sb + OFF_TMEM));

    pdl_trigger();   // successor prologue may begin
    pdl_wait();      // predecessor data must be complete before any global read

    if (tid < 128) {
        const int a = tid >> 3;
        const int c = tid & 7;
        uint32_t o0 = (uint32_t)(a * 128 + c * 16);
        const uint32_t swz = o0 ^ ((o0 >> 3) & 0x70);
        const long long str16 = 16LL * K;

        int s = 0; uint32_t eph = 1;
        for (int t = blockIdx.x; t < T; t += GRID) {
            const int tz = t / gxy;
            const int rem = t - tz * gxy;
            const int ty = rem / gx;
            const int tx = rem - ty * gx;
            const float* pA = A  + (long long)tz * sA + (long long)(ty * TMM + a) * K + c * 4;
            const float* pB = Bt + (long long)tz * sB + (long long)(tx * TN  + a) * K + c * 4;
            for (int kt = 0; kt < nk; kt++) {
                mbar_wait(sb + OFF_EMPTY(s), eph);
                const uint32_t st = sb + 1024 + s * STAGE_BYTES;
                #pragma unroll
                for (int m = 0; m < 16; m++)
                    cp16(st + swz + m * 2048, pA + m * str16);
                #pragma unroll
                for (int m = 0; m < 16; m++)
                    cp16(st + swz + 32768 + m * 2048, pB + m * str16);
                cpasync_arrive(sb + OFF_FULL(s));
                pA += TK; pB += TK;
                if (++s == NS) { s = 0; eph ^= 1; }
            }
        }
    } else if (tid < 256) {
        const int lane = tid & 31;
        const int sp = wid & 3;
        int n = 0;
        for (int t = blockIdx.x; t < T; t += GRID, n++) {
            mbar_wait(sb + OFF_FIN, n & 1);
            TC_FENCE_AFTER();
            const int tz = t / gxy;
            const int rem = t - tz * gxy;
            const int ty = rem / gx;
            const int tx = rem - ty * gx;
            const int bm = ty * TMM, bn = tx * TN;
            const float* biasz = bias ? bias + (long long)tz * sBias : nullptr;

            #pragma unroll 1
            for (int h = 0; h < 2; h++) {
                const long long row = bm + h * 128 + sp * 32 + lane;
                float* crow = C + (long long)tz * sC + row * (long long)N + bn;
                const float* rrow = resid ? resid + (long long)tz * sC + row * (long long)N + bn
                                          : nullptr;
                float brow = 0.0f;
                if (BROW && biasz) brow = biasz[row];
                const uint32_t tmh = tmem + h * 256;

                #pragma unroll 1
                for (int cb = 0; cb < 8; cb++) {
                    uint32_t r[32];
                    LDTM_X32(r, tmh + cb * 32);
                    TC_WAIT_LD();
                    float v[32];
                    #pragma unroll
                    for (int j = 0; j < 32; j++) v[j] = __uint_as_float(r[j]) * alpha;
                    if (biasz) {
                        if (BROW) {
                            #pragma unroll
                            for (int j = 0; j < 32; j++) v[j] += brow;
                        } else {
                            #pragma unroll
                            for (int j0 = 0; j0 < 32; j0 += 4) {
                                float4 bb = *reinterpret_cast<const float4*>(biasz + bn + cb * 32 + j0);
                                v[j0+0] += bb.x; v[j0+1] += bb.y; v[j0+2] += bb.z; v[j0+3] += bb.w;
                            }
                        }
                    }
                    if (rrow) {
                        #pragma unroll
                        for (int j0 = 0; j0 < 32; j0 += 4) {
                            float4 rv = *reinterpret_cast<const float4*>(rrow + cb * 32 + j0);
                            v[j0+0] += rv.x; v[j0+1] += rv.y; v[j0+2] += rv.z; v[j0+3] += rv.w;
                        }
                    }
                    if constexpr (ACT == 1) {
                        #pragma unroll
                        for (int j = 0; j < 32; j++)
                            v[j] = 0.5f * v[j] * (1.0f + erff(v[j] * 0.70710678118654752f));
                    }
                    if constexpr (ROUND) {
                        #pragma unroll
                        for (int j = 0; j < 32; j++) v[j] = rna_tf32(v[j]);
                    }
                    #pragma unroll
                    for (int j0 = 0; j0 < 32; j0 += 4) {
                        float4 o; o.x = v[j0]; o.y = v[j0+1]; o.z = v[j0+2]; o.w = v[j0+3];
                        *reinterpret_cast<float4*>(crow + cb * 32 + j0) = o;
                    }
                }
            }
            TC_FENCE_BEFORE();
            mbar_arrive(sb + OFF_TFREE);
        }
    } else {
        uint32_t ep = elect_one();
        int s = 0; uint32_t ph = 0; int n = 0;
        for (int t = blockIdx.x; t < T; t += GRID, n++) {
            mbar_wait(sb + OFF_TFREE, (n + 1) & 1);
            TC_FENCE_AFTER();
            for (int kt = 0; kt < nk; kt++) {
                mbar_wait(sb + OFF_FULL(s), ph);
                if (ep) {
                    const uint32_t st = sb + 1024 + s * STAGE_BYTES;
                    uint64_t ad0 = make_desc(st);
                    uint64_t ad1 = make_desc(st + 16384);
                    uint64_t bd  = make_desc(st + 32768);
                    const uint32_t en0 = (uint32_t)(kt != 0);
                    #pragma unroll
                    for (int j = 0; j < 4; j++) {
                        const uint32_t en = en0 | (uint32_t)(j != 0);
                        mma_tf32(tmem,       ad0 + 2 * j, bd + 2 * j, IDESC, en);
                        mma_tf32(tmem + 256, ad1 + 2 * j, bd + 2 * j, IDESC, en);
                    }
                    TC_COMMIT(sb + OFF_EMPTY(s));
                    if (kt == nk - 1) TC_COMMIT(sb + OFF_FIN);
                }
                if (++s == NS) { s = 0; ph ^= 1; }
            }
        }
    }

    __syncthreads();
    if (wid == 8) TC_DEALLOC(tmem, 512);
#endif // HAS_TC
}

// ---------------- merged QKV GEMM (R10, proven) ---------------------------------
struct QkvTile {
    const float* pA; const float* pB; float* pC;
    const float* bias; int browMode; int bm; int bn;
};
__device__ __forceinline__ QkvTile qkv_tile(int t, const float* xr, const float* wt,
                                            const float* b2qk, const float* bv,
                                            float* qk, float* vt)
{
    QkvTile d;
    const long long ME = (long long)MTOT * Ed;
    const long long SE = (long long)Sd * Ed;
    const long long EE = (long long)Ed * Ed;
    if (t < 256) {
        const int tz = t >> 7, r = t & 127, ty = r >> 2, tx = r & 3;
        d.pA = xr + (long long)ty * TMM * Ed;
        d.pB = wt + tz * EE + (long long)tx * TN * Ed;
        d.pC = qk + tz * ME;
        d.bias = b2qk + tz * Ed;
        d.browMode = 0;
        d.bm = ty * TMM; d.bn = tx * TN;
    } else {
        const int u = t - 256, tz = u >> 4, r = u & 15, ty = r >> 2, tx = r & 3;
        d.pA = wt + 2 * EE + (long long)ty * TMM * Ed;
        d.pB = xr + tz * SE + (long long)tx * TN * Ed;
        d.pC = vt + tz * SE;
        d.bias = bv;
        d.browMode = 1;
        d.bm = ty * TMM; d.bn = tx * TN;
    }
    return d;
}

__global__ void __launch_bounds__(NTHREADS, 1)
tc_gemm_qkv(const float* __restrict__ xr, const float* __restrict__ wt,
            const float* __restrict__ b2qk, const float* __restrict__ bv,
            float* __restrict__ qk, float* __restrict__ vt)
{
#if HAS_TC
    extern __shared__ char smem[];
    const uint32_t sb = smem_u32(smem);
    const int tid = threadIdx.x;
    const int wid = tid >> 5;
    const int K = Ed, N = Ed, nk = Ed / TK;
    const int T = 384;

    if (tid == 0) {
        for (int s = 0; s < NS; s++) {
            mbar_init(sb + OFF_FULL(s), 128);
            mbar_init(sb + OFF_EMPTY(s), 1);
        }
        mbar_init(sb + OFF_FIN, 1);
        mbar_init(sb + OFF_TFREE, 128);
    }
    if (wid == 8) {
        TC_ALLOC(sb + OFF_TMEM, 512);
        TC_RELINQ();
    }
    __syncthreads();
    uint32_t tmem;
    asm volatile("ld.shared.b32 %0, [%1];" : "=r"(tmem) : "r"(sb + OFF_TMEM));

    pdl_trigger();
    pdl_wait();

    if (tid < 128) {
        const int a = tid >> 3;
        const int c = tid & 7;
        uint32_t o0 = (uint32_t)(a * 128 + c * 16);
        const uint32_t swz = o0 ^ ((o0 >> 3) & 0x70);
        const long long str16 = 16LL * K;

        int s = 0; uint32_t eph = 1;
        for (int t = blockIdx.x; t < T; t += GRID) {
            QkvTile d = qkv_tile(t, xr, wt, b2qk, bv, qk, vt);
            const float* pA = d.pA + (long long)a * K + c * 4;
            const float* pB = d.pB + (long long)a * K + c * 4;
            for (int kt = 0; kt < nk; kt++) {
                mbar_wait(sb + OFF_EMPTY(s), eph);
                const uint32_t st = sb + 1024 + s * STAGE_BYTES;
                #pragma unroll
                for (int m = 0; m < 16; m++)
                    cp16(st + swz + m * 2048, pA + m * str16);
                #pragma unroll
                for (int m = 0; m < 16; m++)
                    cp16(st + swz + 32768 + m * 2048, pB + m * str16);
                cpasync_arrive(sb + OFF_FULL(s));
                pA += TK; pB += TK;
                if (++s == NS) { s = 0; eph ^= 1; }
            }
        }
    } else if (tid < 256) {
        const int lane = tid & 31;
        const int sp = wid & 3;
        int n = 0;
        for (int t = blockIdx.x; t < T; t += GRID, n++) {
            mbar_wait(sb + OFF_FIN, n & 1);
            TC_FENCE_AFTER();
            QkvTile d = qkv_tile(t, xr, wt, b2qk, bv, qk, vt);

            #pragma unroll 1
            for (int h = 0; h < 2; h++) {
                const long long lrow = h * 128 + sp * 32 + lane;
                float* crow = d.pC + (d.bm + lrow) * (long long)N + d.bn;
                float brow = 0.0f;
                if (d.browMode) brow = d.bias[d.bm + lrow];
                const uint32_t tmh = tmem + h * 256;

                #pragma unroll 1
                for (int cb = 0; cb < 8; cb++) {
                    uint32_t r[32];
                    LDTM_X32(r, tmh + cb * 32);
                    TC_WAIT_LD();
                    float v[32];
                    #pragma unroll
                    for (int j = 0; j < 32; j++) v[j] = __uint_as_float(r[j]);
                    if (d.browMode) {
                        #pragma unroll
                        for (int j = 0; j < 32; j++) v[j] += brow;
                    } else {
                        #pragma unroll
                        for (int j0 = 0; j0 < 32; j0 += 4) {
                            float4 bb = *reinterpret_cast<const float4*>(d.bias + d.bn + cb * 32 + j0);
                            v[j0+0] += bb.x; v[j0+1] += bb.y; v[j0+2] += bb.z; v[j0+3] += bb.w;
                        }
                    }
                    #pragma unroll
                    for (int j = 0; j < 32; j++) v[j] = rna_tf32(v[j]);
                    #pragma unroll
                    for (int j0 = 0; j0 < 32; j0 += 4) {
                        float4 o; o.x = v[j0]; o.y = v[j0+1]; o.z = v[j0+2]; o.w = v[j0+3];
                        *reinterpret_cast<float4*>(crow + cb * 32 + j0) = o;
                    }
                }
            }
            TC_FENCE_BEFORE();
            mbar_arrive(sb + OFF_TFREE);
        }
    } else {
        uint32_t ep = elect_one();
        int s = 0; uint32_t ph = 0; int n = 0;
        for (int t = blockIdx.x; t < T; t += GRID, n++) {
            mbar_wait(sb + OFF_TFREE, (n + 1) & 1);
            TC_FENCE_AFTER();
            for (int kt = 0; kt < nk; kt++) {
                mbar_wait(sb + OFF_FULL(s), ph);
                if (ep) {
                    const uint32_t st = sb + 1024 + s * STAGE_BYTES;
                    uint64_t ad0 = make_desc(st);
                    uint64_t ad1 = make_desc(st + 16384);
                    uint64_t bd  = make_desc(st + 32768);
                    const uint32_t en0 = (uint32_t)(kt != 0);
                    #pragma unroll
                    for (int j = 0; j < 4; j++) {
                        const uint32_t en = en0 | (uint32_t)(j != 0);
                        mma_tf32(tmem,       ad0 + 2 * j, bd + 2 * j, IDESC, en);
                        mma_tf32(tmem + 256, ad1 + 2 * j, bd + 2 * j, IDESC, en);
                    }
                    TC_COMMIT(sb + OFF_EMPTY(s));
                    if (kt == nk - 1) TC_COMMIT(sb + OFF_FIN);
                }
                if (++s == NS) { s = 0; ph ^= 1; }
            }
        }
    }

    __syncthreads();
    if (wid == 8) TC_DEALLOC(tmem, 512);
#endif // HAS_TC
}

// ---------------- elementwise kernels ---------------------------------------
__device__ __forceinline__ float block_sum(float v, float* sh) {
    const int lane = threadIdx.x & 31, w = threadIdx.x >> 5;
    #pragma unroll
    for (int o = 16; o; o >>= 1) v += __shfl_xor_sync(0xffffffffu, v, o);
    __syncthreads();
    if (lane == 0) sh[w] = v;
    __syncthreads();
    float s = 0.f;
    #pragma unroll
    for (int i = 0; i < 8; i++) s += sh[i];
    return s;
}
__device__ __forceinline__ float block_max(float v, float* sh) {
    const int lane = threadIdx.x & 31, w = threadIdx.x >> 5;
    #pragma unroll
    for (int o = 16; o; o >>= 1) v = fmaxf(v, __shfl_xor_sync(0xffffffffu, v, o));
    __syncthreads();
    if (lane == 0) sh[w] = v;
    __syncthreads();
    float s = -INFINITY;
    #pragma unroll
    for (int i = 0; i < 8; i++) s = fmaxf(s, sh[i]);
    return s;
}

__global__ void __launch_bounds__(256) softmax_kernel(float* __restrict__ data)
{
    __shared__ float sh[8];
    pdl_trigger();
    pdl_wait();
    const long long row = blockIdx.x;
    float4* p = reinterpret_cast<float4*>(data + row * 1024);
    float4 x = p[threadIdx.x];
    float m = fmaxf(fmaxf(x.x, x.y), fmaxf(x.z, x.w));
    m = block_max(m, sh);
    x.x = expf(x.x - m); x.y = expf(x.y - m);
    x.z = expf(x.z - m); x.w = expf(x.w - m);
    float s = x.x + x.y + x.z + x.w;
    s = block_sum(s, sh);
    const float inv = 1.0f / s;
    x.x = rna_tf32(x.x * inv); x.y = rna_tf32(x.y * inv);
    x.z = rna_tf32(x.z * inv); x.w = rna_tf32(x.w * inv);
    p[threadIdx.x] = x;
}

template<bool ROUND>
__global__ void __launch_bounds__(256)
ln_kernel(const float* __restrict__ in, const float* __restrict__ g,
          const float* __restrict__ b, float* __restrict__ out)
{
    __shared__ float sh[8];
    pdl_trigger();
    pdl_wait();
    const long long row = blockIdx.x;
    const float4* p = reinterpret_cast<const float4*>(in + row * 1024);
    float4 x = p[threadIdx.x];
    float s = x.x + x.y + x.z + x.w;
    s = block_sum(s, sh);
    const float mu = s * (1.0f / 1024.0f);
    const float dx = x.x - mu, dy = x.y - mu, dz = x.z - mu, dw = x.w - mu;
    float ss = dx * dx + dy * dy + dz * dz + dw * dw;
    ss = block_sum(ss, sh);
    const float rstd = rsqrtf(ss * (1.0f / 1024.0f) + 1e-12f);
    const float4 gg = reinterpret_cast<const float4*>(g)[threadIdx.x];
    const float4 bb = reinterpret_cast<const float4*>(b)[threadIdx.x];
    float4 o;
    o.x = dx * rstd * gg.x + bb.x;
    o.y = dy * rstd * gg.y + bb.y;
    o.z = dz * rstd * gg.z + bb.z;
    o.w = dw * rstd * gg.w + bb.w;
    if (ROUND) { o.x = rna_tf32(o.x); o.y = rna_tf32(o.y); o.z = rna_tf32(o.z); o.w = rna_tf32(o.w); }
    reinterpret_cast<float4*>(out + row * 1024)[threadIdx.x] = o;
}

// Fast 64x64 transpose body.
__device__ __forceinline__ void transpose_body(const float* __restrict__ in,
                                               float* __restrict__ out,
                                               int R, int C, int r0, int c0)
{
    __shared__ float t[64][65];
    const int fc = (threadIdx.x & 15) * 4;
    const int fr = threadIdx.x >> 4;

    #pragma unroll
    for (int i = 0; i < 4; i++) {
        const int r = fr + i * 16;
        float4 x = *reinterpret_cast<const float4*>(in + (long long)(r0 + r) * C + c0 + fc);
        t[fc + 0][r] = x.x; t[fc + 1][r] = x.y; t[fc + 2][r] = x.z; t[fc + 3][r] = x.w;
    }
    __syncthreads();
    #pragma unroll
    for (int i = 0; i < 4; i++) {
        const int oc = fr + i * 16;
        float4 y;
        y.x = rna_tf32(t[oc][fc + 0]); y.y = rna_tf32(t[oc][fc + 1]);
        y.z = rna_tf32(t[oc][fc + 2]); y.w = rna_tf32(t[oc][fc + 3]);
        *reinterpret_cast<float4*>(out + (long long)(c0 + oc) * R + r0 + fc) = y;
    }
}

// Prep 1: blocks [0,1024): grid-stride RNA-round of x into xr.
//         blocks 1024,1025: copy bq/bk into b2.
//         blocks [1026, 2050): transpose Wq/Wk/Wv/Wd.
__global__ void __launch_bounds__(256)
prep1_kernel(const float4* __restrict__ x, float4* __restrict__ xr, long long n4,
             const float4* __restrict__ bq, const float4* __restrict__ bk, float4* __restrict__ b2,
             const float* __restrict__ Wq, const float* __restrict__ Wk,
             const float* __restrict__ Wv, const float* __restrict__ Wd,
             float* __restrict__ oq, float* __restrict__ ok,
             float* __restrict__ ov, float* __restrict__ od)
{
    pdl_trigger();   // lets prep2 (independent) co-run
    const int b = blockIdx.x;
    if (b < 1024) {
        for (long long i = b * 256LL + threadIdx.x; i < n4; i += 1024LL * 256LL) {
            float4 v = x[i];
            v.x = rna_tf32(v.x); v.y = rna_tf32(v.y);
            v.z = rna_tf32(v.z); v.w = rna_tf32(v.w);
            xr[i] = v;
        }
    } else if (b < 1026) {
        const float4* src = (b == 1024) ? bq : bk;
        b2[(b - 1024) * 256 + threadIdx.x] = src[threadIdx.x];
    } else {
        const int idx = b - 1026;
        const int w = idx >> 8;
        const int r = (idx & 255) >> 4;
        const int c = idx & 15;
        const float* in = w == 0 ? Wq : w == 1 ? Wk : w == 2 ? Wv : Wd;
        float* out      = w == 0 ? oq : w == 1 ? ok : w == 2 ? ov : od;
        transpose_body(in, out, 1024, 1024, r * 64, c * 64);
    }
}

// Prep 2: independent of prep1 (reads only Wi/Wo) -> runs concurrently via PDL.
__global__ void __launch_bounds__(256)
prep2_kernel(const float* __restrict__ Wi, float* __restrict__ wit,
             const float* __restrict__ Wo, float* __restrict__ wot)
{
    pdl_trigger();
    const int b = blockIdx.x;
    if (b < 1024) {
        const int cx = b & 63, ry = b >> 6;
        transpose_body(Wi, wit, Ed, Fd, ry * 64, cx * 64);
    } else {
        const int idx = b - 1024;
        const int cx = idx & 15, ry = idx >> 4;
        transpose_body(Wo, wot, Fd, Ed, ry * 64, cx * 64);
    }
}

// ---------------- host launcher -----------------------------------------------
extern "C" void kernel_launch(void* const* d_in, const int* in_sizes, int n_in,
                              void* d_out, int out_size)
{
    const float* x  = (const float*)d_in[0];
    const float* Wq = (const float*)d_in[1];
    const float* bq = (const float*)d_in[2];
    const float* Wk = (const float*)d_in[3];
    const float* bk = (const float*)d_in[4];
    const float* Wv = (const float*)d_in[5];
    const float* bv = (const float*)d_in[6];
    const float* Wd = (const float*)d_in[7];
    const float* bd = (const float*)d_in[8];
    const float* g1 = (const float*)d_in[9];
    const float* b1 = (const float*)d_in[10];
    const float* Wi = (const float*)d_in[11];
    const float* bi = (const float*)d_in[12];
    const float* Wo = (const float*)d_in[13];
    const float* bo = (const float*)d_in[14];
    const float* g2 = (const float*)d_in[15];
    const float* b2 = (const float*)d_in[16];
    float* out = (float*)d_out;

    float *xr, *qk, *vt, *at, *ao, *tmp, *h1, *ff;
    float *wt, *b2qk, *wdt, *wit, *wot;
    cudaGetSymbolAddress((void**)&xr,   g_xr);
    cudaGetSymbolAddress((void**)&qk,   g_qk);
    cudaGetSymbolAddress((void**)&vt,   g_vt);
    cudaGetSymbolAddress((void**)&at,   g_at);
    cudaGetSymbolAddress((void**)&ao,   g_ao);
    cudaGetSymbolAddress((void**)&tmp,  g_tmp);
    cudaGetSymbolAddress((void**)&h1,   g_h1);
    cudaGetSymbolAddress((void**)&ff,   g_ff);
    cudaGetSymbolAddress((void**)&wt,   g_wt);
    cudaGetSymbolAddress((void**)&b2qk, g_b2);
    cudaGetSymbolAddress((void**)&wdt,  g_wdt);
    cudaGetSymbolAddress((void**)&wit,  g_wit);
    cudaGetSymbolAddress((void**)&wot,  g_wot);

    cudaFuncSetAttribute(tc_gemm_qkv,              cudaFuncAttributeMaxDynamicSharedMemorySize, SMEM_TOTAL);
    cudaFuncSetAttribute(tc_gemm<0, true,  false>, cudaFuncAttributeMaxDynamicSharedMemorySize, SMEM_TOTAL);
    cudaFuncSetAttribute(tc_gemm<0, false, false>, cudaFuncAttributeMaxDynamicSharedMemorySize, SMEM_TOTAL);
    cudaFuncSetAttribute(tc_gemm<1, true,  false>, cudaFuncAttributeMaxDynamicSharedMemorySize, SMEM_TOTAL);

    const long long ME = (long long)MTOT * Ed;
    const long long SE = (long long)Sd * Ed;
    const long long SS = (long long)Sd * Sd;
    const long long EE = (long long)Ed * Ed;
    float* q = qk;
    float* k = qk + ME;

    // PDL launch plumbing
    cudaLaunchAttribute pdlAttr[1];
    pdlAttr[0].id = cudaLaunchAttributeProgrammaticStreamSerialization;
    pdlAttr[0].val.programmaticStreamSerializationAllowed = 1;

    auto launch = [&](auto kern, dim3 g, dim3 b, size_t sm, bool pdl, auto... args) {
        cudaLaunchConfig_t cfg{};
        cfg.gridDim = g; cfg.blockDim = b;
        cfg.dynamicSmemBytes = sm;
        cfg.stream = 0;
        cfg.attrs = pdl ? pdlAttr : nullptr;
        cfg.numAttrs = pdl ? 1 : 0;
        cudaLaunchKernelEx(&cfg, kern, args...);
    };

    const float* nullf = nullptr;

    // 0: prep1 (no PDL: first kernel)
    launch(prep1_kernel, dim3(2050), dim3(256), 0, false,
           (const float4*)x, (float4*)xr, (long long)(ME / 4),
           (const float4*)bq, (const float4*)bk, (float4*)b2qk,
           Wq, Wk, Wv, Wd, wt, wt + EE, wt + 2 * EE, wdt);
    // 1: prep2 (PDL -> co-runs with prep1; independent data)
    launch(prep2_kernel, dim3(2048), dim3(256), 0, true, Wi, wit, Wo, wot);
    // 2: merged QKV (needs prep1; predecessor prep2 completes after prep1 -> safe)
    launch(tc_gemm_qkv, dim3(GRID), dim3(NTHREADS), (size_t)SMEM_TOTAL, true,
           xr, wt, (const float*)b2qk, bv, qk, vt);
    // 3: scores = q @ k^T / 32  <-- profiled launch
    launch(tc_gemm<0, false, false>, dim3(GRID), dim3(NTHREADS), (size_t)SMEM_TOTAL, true,
           (const float*)q, (const float*)k, nullf, nullf, at,
           (int)Ed, (int)Sd, 0.03125f, SE, SE, SS, 0LL, 128, 4, 16);
    // 4: softmax
    launch(softmax_kernel, dim3(Bd * Sd), dim3(256), 0, true, at);
    // 5: attn_out = attn_w @ v
    launch(tc_gemm<0, true, false>, dim3(GRID), dim3(NTHREADS), (size_t)SMEM_TOTAL, true,
           (const float*)at, (const float*)vt, nullf, nullf, ao,
           (int)Sd, (int)Ed, 1.0f, SS, SE, SE, 0LL, 128, 4, 16);
    // 6: tmp = ao @ Wd + bd + x
    launch(tc_gemm<0, false, false>, dim3(GRID), dim3(NTHREADS), (size_t)SMEM_TOTAL, true,
           (const float*)ao, (const float*)wdt, bd, x, tmp,
           (int)Ed, (int)Ed, 1.0f, 0LL, 0LL, 0LL, 0LL, 128, 4, 128);
    // 7: h1 = LN(tmp)
    launch(ln_kernel<true>, dim3(MTOT), dim3(256), 0, true,
           (const float*)tmp, g1, b1, h1);
    // 8: ff = gelu(h1 @ Wi + bi)
    launch(tc_gemm<1, true, false>, dim3(GRID), dim3(NTHREADS), (size_t)SMEM_TOTAL, true,
           (const float*)h1, (const float*)wit, bi, nullf, ff,
           (int)Ed, (int)Fd, 1.0f, 0LL, 0LL, 0LL, 0LL, 512, 16, 512);
    // 9: tmp = ff @ Wo + bo + h1
    launch(tc_gemm<0, false, false>, dim3(GRID), dim3(NTHREADS), (size_t)SMEM_TOTAL, true,
           (const float*)ff, (const float*)wot, bo, (const float*)h1, tmp,
           (int)Fd, (int)Ed, 1.0f, 0LL, 0LL, 0LL, 0LL, 128, 4, 128);
    // 10: out = LN(tmp)
    launch(ln_kernel<false>, dim3(MTOT), dim3(256), 0, true,
           (const float*)tmp, g2, b2, out);
}